// round 17
// baseline (speedup 1.0000x reference)
#include <cuda_runtime.h>
#include <cuda_bf16.h>
#include <math.h>
#include <cstdint>

#define BB    4
#define NN    4096
#define FIN   256
#define FOUT  128
#define GALPHA 0.2f

#define KT      64                 // m-columns per tile
#define NTILES  (NN / KT)          // 64

// ---- device scratch ----
__device__ __align__(16) float g_Wh[BB * NN * FOUT];            // [b][m][f] fp32
__device__ __align__(16) __nv_bfloat16 g_WhTh[BB * FOUT * NN];  // [b][f][m] hi
__device__ __align__(16) __nv_bfloat16 g_WhTl[BB * FOUT * NN];  // [b][f][m] lo
__device__ float g_Wh1[BB * NN];
__device__ __align__(16) float4 g_cf[BB * NN];                  // (w2, e^w2, e^aw2, 0)

// ---------------------------------------------------------------------------
// PTX helpers (plain sm_80+ only: .target sm_103 safe)
// ---------------------------------------------------------------------------
__device__ __forceinline__ uint32_t smem_u32(const void* p) {
    uint32_t a;
    asm("{ .reg .u64 t; cvta.to.shared.u64 t, %1; cvt.u32.u64 %0, t; }" : "=r"(a) : "l"(p));
    return a;
}
__device__ __forceinline__ void cp16(uint32_t saddr, const void* g) {
    asm volatile("cp.async.cg.shared.global [%0], [%1], 16;" :: "r"(saddr), "l"(g));
}
__device__ __forceinline__ void cp_commit() { asm volatile("cp.async.commit_group;"); }
template <int N>
__device__ __forceinline__ void cp_wait() { asm volatile("cp.async.wait_group %0;" :: "n"(N)); }

__device__ __forceinline__ void bar_sync(int id) {
    asm volatile("bar.sync %0, 384;" :: "r"(id) : "memory");
}
__device__ __forceinline__ void bar_arrive(int id) {
    asm volatile("bar.arrive %0, 384;" :: "r"(id) : "memory");
}
__device__ __forceinline__ void bar_sync_n(int id, int n) {
    asm volatile("bar.sync %0, %1;" :: "r"(id), "r"(n) : "memory");
}

__device__ __forceinline__ void ldsm_x4(uint32_t* r, uint32_t addr) {
    asm volatile("ldmatrix.sync.aligned.m8n8.x4.shared.b16 {%0,%1,%2,%3}, [%4];"
                 : "=r"(r[0]), "=r"(r[1]), "=r"(r[2]), "=r"(r[3]) : "r"(addr));
}
__device__ __forceinline__ void mma16816(float* c, const uint32_t* a, uint32_t b0, uint32_t b1) {
    asm volatile(
        "mma.sync.aligned.m16n8k16.row.col.f32.bf16.bf16.f32 "
        "{%0,%1,%2,%3}, {%4,%5,%6,%7}, {%8,%9}, {%0,%1,%2,%3};"
        : "+f"(c[0]), "+f"(c[1]), "+f"(c[2]), "+f"(c[3])
        : "r"(a[0]), "r"(a[1]), "r"(a[2]), "r"(a[3]), "r"(b0), "r"(b1));
}

// ---------------------------------------------------------------------------
// Kernel A: Wh = h @ W (unchanged)
// ---------------------------------------------------------------------------
__global__ __launch_bounds__(256) void wh_gemm_kernel(const float* __restrict__ h,
                                                      const float* __restrict__ W) {
    __shared__ float hs[64][33];
    __shared__ float Ws[32][FOUT];
    const int t  = threadIdx.x;
    const int r0 = blockIdx.x * 64;
    const int cg = (t & 15) * 8;
    const int rg = (t >> 4) * 4;

    float acc[4][8];
#pragma unroll
    for (int r = 0; r < 4; ++r)
#pragma unroll
        for (int c = 0; c < 8; ++c) acc[r][c] = 0.f;

    for (int kt = 0; kt < FIN; kt += 32) {
#pragma unroll
        for (int i = 0; i < 8; ++i) {
            int e = t + i * 256;
            hs[e >> 5][e & 31] = h[(size_t)(r0 + (e >> 5)) * FIN + kt + (e & 31)];
        }
#pragma unroll
        for (int i = 0; i < 16; ++i) {
            int e = t + i * 256;
            Ws[e >> 7][e & 127] = W[(size_t)(kt + (e >> 7)) * FOUT + (e & 127)];
        }
        __syncthreads();
#pragma unroll
        for (int kk = 0; kk < 32; ++kk) {
            float av[4];
#pragma unroll
            for (int r = 0; r < 4; ++r) av[r] = hs[rg + r][kk];
            float4 b0 = *(const float4*)&Ws[kk][cg];
            float4 b1 = *(const float4*)&Ws[kk][cg + 4];
            float bv[8] = {b0.x, b0.y, b0.z, b0.w, b1.x, b1.y, b1.z, b1.w};
#pragma unroll
            for (int r = 0; r < 4; ++r)
#pragma unroll
                for (int c = 0; c < 8; ++c)
                    acc[r][c] += av[r] * bv[c];
        }
        __syncthreads();
    }
#pragma unroll
    for (int r = 0; r < 4; ++r)
#pragma unroll
        for (int c = 0; c < 8; ++c)
            g_Wh[(size_t)(r0 + rg + r) * FOUT + cg + c] = acc[r][c];
}

// ---------------------------------------------------------------------------
// Kernel B: row projections + global column-factor table (unchanged)
// ---------------------------------------------------------------------------
__global__ __launch_bounds__(256) void proj_kernel(const float* __restrict__ a) {
    const int row  = blockIdx.x * 8 + (threadIdx.x >> 5);
    const int lane = threadIdx.x & 31;
    const float* wh = g_Wh + (size_t)row * FOUT;
    float s1 = 0.f, s2 = 0.f;
#pragma unroll
    for (int i = 0; i < 4; ++i) {
        int k = lane + 32 * i;
        float v = wh[k];
        s1 += v * a[k];
        s2 += v * a[FOUT + k];
    }
#pragma unroll
    for (int o = 16; o > 0; o >>= 1) {
        s1 += __shfl_down_sync(0xffffffffu, s1, o);
        s2 += __shfl_down_sync(0xffffffffu, s2, o);
    }
    if (lane == 0) {
        g_Wh1[row] = s1;
        g_cf[row]  = make_float4(s2, __expf(s2), __expf(GALPHA * s2), 0.f);
    }
}

// ---------------------------------------------------------------------------
// Kernel B2: WhT hi/lo bf16 split (unchanged)
// ---------------------------------------------------------------------------
__global__ __launch_bounds__(256) void transpose_split_kernel() {
    __shared__ float tile[32][33];
    const int tx = threadIdx.x, ty = threadIdx.y;
    const int m0 = blockIdx.x * 32;
    const int f0 = blockIdx.y * 32;
    const int b  = blockIdx.z;
#pragma unroll
    for (int k = 0; k < 4; ++k)
        tile[ty + k * 8][tx] = g_Wh[(size_t)(b * NN + m0 + ty + k * 8) * FOUT + f0 + tx];
    __syncthreads();
#pragma unroll
    for (int k = 0; k < 4; ++k) {
        float v = tile[tx][ty + k * 8];
        __nv_bfloat16 hi = __float2bfloat16(v);
        __nv_bfloat16 lo = __float2bfloat16(v - __bfloat162float(hi));
        size_t o = (size_t)(b * FOUT + f0 + ty + k * 8) * NN + m0 + tx;
        g_WhTh[o] = hi;
        g_WhTl[o] = lo;
    }
}

// ---------------------------------------------------------------------------
// Kernel C: warp-specialized fused attention, deep-pipelined.
//   Swizzled 128B-row smem layout (no pad). A: 2 stages, B: 4 stages
//   (issued 2 tiles ahead), CF: 3 stages. adj lives in producer registers,
//   LDG-prefetched 1 tile ahead. One cp.async wait per tile, no same-tile
//   gmem dependency anywhere.
// ---------------------------------------------------------------------------
#define HTILE      16384                    // 128 rows x 128 B (one bf16 half-tile)
#define STAGE_AB   (2 * HTILE)              // hi + lo
#define OFF_A      0                        // 2 stages
#define OFF_B      (OFF_A + 2 * STAGE_AB)   // 4 stages
#define OFF_CF     (OFF_B + 4 * STAGE_AB)   // 3 stages x 1024
#define OFF_DENS   (OFF_CF + 3 * 1024)
#define SMEM_TOTAL (OFF_DENS + 512)         // 200192 B

__global__ __launch_bounds__(384, 1) void gat_attn_ws(const int* __restrict__ adj,
                                                      float* __restrict__ out) {
    extern __shared__ __align__(1024) char sm[];
    const uint32_t smb = smem_u32(sm);
    float* dens = (float*)(sm + OFF_DENS);

    const int t    = threadIdx.x;
    const int wid  = t >> 5;
    const int lane = t & 31;
    const int b    = blockIdx.y;
    const int n0   = blockIdx.x * 128;

    if (wid >= 8) {
        // =============================== PRODUCER ===========================
        const int r = t - 256;             // 0..127, owns n-row r
        const float myw1 = g_Wh1[b * NN + n0 + r];
        const float myep = __expf(myw1);
        const float myen = __expf(GALPHA * myw1);
        const int4* gadj4 = (const int4*)(adj + (size_t)(b * NN + n0 + r) * NN);
        const uint32_t wx = (uint32_t)((r & 7) << 4);
        const uint32_t rowb = (uint32_t)(r * 128);

        // adj(0) into registers
        int4 aj[16];
#pragma unroll
        for (int j = 0; j < 16; ++j) aj[j] = gadj4[j];

        // preamble: commit [B(0)+CF(0)], [B(1)+CF(1)]
#pragma unroll
        for (int pp = 0; pp < 2; ++pp) {
            const int mtn = pp * KT;
            uint32_t bh = smb + OFF_B + (pp & 3) * STAGE_AB;
#pragma unroll
            for (int j = 0; j < 8; ++j) {
                int idx = r + j * 128;
                int f = idx >> 3, c = idx & 7;
                uint32_t o = (uint32_t)(f * 128 + c * 16);
                o ^= (o >> 3) & 0x70;
                size_t go = (size_t)(b * FOUT + f) * NN + mtn + c * 8;
                cp16(bh + o, g_WhTh + go);
                cp16(bh + HTILE + o, g_WhTl + go);
            }
            if (r < 64)
                cp16(smb + OFF_CF + (pp % 3) * 1024 + r * 16, &g_cf[b * NN + mtn + r]);
            cp_commit();
        }

        float den = 0.f;
        for (int i = 0; i < NTILES; ++i) {
            const int s = i & 1;
            if (i >= 2) bar_sync(3 + s);   // EMPTY[s]: stage s (A) + stage (i+2)&3 (B) free

            // ---- commit [B(i+2) + CF(i+2)] ----
            if (i + 2 < NTILES) {
                const int mtn = (i + 2) * KT;
                uint32_t bh = smb + OFF_B + ((i + 2) & 3) * STAGE_AB;
#pragma unroll
                for (int j = 0; j < 8; ++j) {
                    int idx = r + j * 128;
                    int f = idx >> 3, c = idx & 7;
                    uint32_t o = (uint32_t)(f * 128 + c * 16);
                    o ^= (o >> 3) & 0x70;
                    size_t go = (size_t)(b * FOUT + f) * NN + mtn + c * 8;
                    cp16(bh + o, g_WhTh + go);
                    cp16(bh + HTILE + o, g_WhTl + go);
                }
                if (r < 64)
                    cp16(smb + OFF_CF + ((i + 2) % 3) * 1024 + r * 16,
                         &g_cf[b * NN + mtn + r]);
            }
            cp_commit();

            cp_wait<2>();                  // B(i)+CF(i) landed (committed 2 iters ago)
            bar_sync_n(5, 128);            // producer-scope: CF visible to all 128

            // ---- weight-gen: regs adj + smem cf -> A[s] hi/lo ----
            {
                const float4* cf = (const float4*)(sm + OFF_CF + (i % 3) * 1024);
                char* Ah = sm + OFF_A + s * STAGE_AB;
                char* Al = Ah + HTILE;
#pragma unroll
                for (int g = 0; g < 16; ++g) {
                    const int c = 4 * g;
                    int4 av = aj[g];
                    float4 f0 = cf[c], f1 = cf[c + 1], f2 = cf[c + 2], f3 = cf[c + 3];
                    float w0 = (av.x > 0) ? ((myw1 + f0.x >= 0.f) ? myep * f0.y : myen * f0.z) : 0.f;
                    float w1v = (av.y > 0) ? ((myw1 + f1.x >= 0.f) ? myep * f1.y : myen * f1.z) : 0.f;
                    float w2v = (av.z > 0) ? ((myw1 + f2.x >= 0.f) ? myep * f2.y : myen * f2.z) : 0.f;
                    float w3v = (av.w > 0) ? ((myw1 + f3.x >= 0.f) ? myep * f3.y : myen * f3.z) : 0.f;
                    den += (w0 + w1v) + (w2v + w3v);
                    // truncation hi split (exact lo = w - hi)
                    uint32_t u0 = __float_as_uint(w0), u1 = __float_as_uint(w1v);
                    uint32_t u2 = __float_as_uint(w2v), u3 = __float_as_uint(w3v);
                    float lo0 = w0  - __uint_as_float(u0 & 0xFFFF0000u);
                    float lo1 = w1v - __uint_as_float(u1 & 0xFFFF0000u);
                    float lo2 = w2v - __uint_as_float(u2 & 0xFFFF0000u);
                    float lo3 = w3v - __uint_as_float(u3 & 0xFFFF0000u);
                    uint32_t h01 = __byte_perm(u0, u1, 0x7632);
                    uint32_t h23 = __byte_perm(u2, u3, 0x7632);
                    __nv_bfloat162 l01 = __floats2bfloat162_rn(lo0, lo1);
                    __nv_bfloat162 l23 = __floats2bfloat162_rn(lo2, lo3);
                    uint32_t off = (rowb + (uint32_t)(8 * g)) ^ wx;
                    *(uint2*)(Ah + off) = make_uint2(h01, h23);
                    *(uint2*)(Al + off) = make_uint2(*(uint32_t*)&l01, *(uint32_t*)&l23);
                }
            }

            // ---- prefetch adj(i+1) into registers ----
            if (i + 1 < NTILES) {
#pragma unroll
                for (int j = 0; j < 16; ++j) aj[j] = gadj4[(i + 1) * 16 + j];
            }

            __threadfence_block();         // A stores visible before release
            bar_arrive(1 + s);             // FULL[s]
        }
        dens[r] = den;
        __syncthreads();
    } else {
        // =============================== CONSUMER ===========================
        const int wm = wid & 1;            // warp M (0..1)
        const int wn = wid >> 1;           // warp N (0..3)
        const uint32_t a_row = (uint32_t)(wm * 64 + (lane & 15));
        const uint32_t a_cb  = (uint32_t)((lane >> 4) << 4);      // 0 or 16 bytes
        const uint32_t a_x   = (uint32_t)((lane & 7) << 4);
        const uint32_t b_row = (uint32_t)(wn * 32 + (lane & 7) + ((lane >> 4) << 3));
        const uint32_t b_cb  = (uint32_t)(((lane >> 3) & 1) << 4);
        const uint32_t b_x   = (uint32_t)((lane & 7) << 4);

        float acc[4][4][4];
#pragma unroll
        for (int i = 0; i < 4; ++i)
#pragma unroll
            for (int j = 0; j < 4; ++j)
#pragma unroll
                for (int k = 0; k < 4; ++k) acc[i][j][k] = 0.f;

        for (int i = 0; i < NTILES; ++i) {
            const int s = i & 1;
            bar_sync(1 + s);               // FULL[s]

            const uint32_t sA = smb + OFF_A + s * STAGE_AB + a_row * 128;
            const uint32_t sB = smb + OFF_B + (i & 3) * STAGE_AB + b_row * 128;
#pragma unroll
            for (int ks = 0; ks < 4; ++ks) {
                const uint32_t ka = (a_cb + ks * 32) ^ a_x;
                const uint32_t kb = (b_cb + ks * 32) ^ b_x;
                uint32_t ah[4][4], al[4][4], bh[2][4], bl[2][4];
#pragma unroll
                for (int m4 = 0; m4 < 4; ++m4) {
                    ldsm_x4(ah[m4], sA + m4 * 2048 + ka);
                    ldsm_x4(al[m4], sA + HTILE + m4 * 2048 + ka);
                }
#pragma unroll
                for (int nh = 0; nh < 2; ++nh) {
                    ldsm_x4(bh[nh], sB + nh * 2048 + kb);
                    ldsm_x4(bl[nh], sB + HTILE + nh * 2048 + kb);
                }
#pragma unroll
                for (int m4 = 0; m4 < 4; ++m4)
#pragma unroll
                    for (int nt = 0; nt < 4; ++nt) {
                        const int nh = nt >> 1, sel = (nt & 1) * 2;
                        mma16816(acc[m4][nt], ah[m4], bh[nh][sel], bh[nh][sel + 1]);
                        mma16816(acc[m4][nt], ah[m4], bl[nh][sel], bl[nh][sel + 1]);
                        mma16816(acc[m4][nt], al[m4], bh[nh][sel], bh[nh][sel + 1]);
                    }
            }
            bar_arrive(3 + s);             // EMPTY[s]
        }
        __syncthreads();                   // dens ready

        // ---- epilogue: normalize + ELU + store ----
#pragma unroll
        for (int m4 = 0; m4 < 4; ++m4) {
            const int row0 = wm * 64 + m4 * 16 + (lane >> 2);
            const float inv0 = 1.f / dens[row0];
            const float inv8 = 1.f / dens[row0 + 8];
            float* o0 = out + (size_t)(b * NN + n0 + row0) * FOUT;
            float* o8 = out + (size_t)(b * NN + n0 + row0 + 8) * FOUT;
#pragma unroll
            for (int nt = 0; nt < 4; ++nt) {
                const int col = wn * 32 + nt * 8 + (lane & 3) * 2;
                float y0 = acc[m4][nt][0] * inv0;
                float y1 = acc[m4][nt][1] * inv0;
                float y2 = acc[m4][nt][2] * inv8;
                float y3 = acc[m4][nt][3] * inv8;
                float2 v0 = make_float2((y0 > 0.f) ? y0 : expm1f(y0),
                                        (y1 > 0.f) ? y1 : expm1f(y1));
                float2 v8 = make_float2((y2 > 0.f) ? y2 : expm1f(y2),
                                        (y3 > 0.f) ? y3 : expm1f(y3));
                *(float2*)(o0 + col) = v0;
                *(float2*)(o8 + col) = v8;
            }
        }
    }
}

// ---------------------------------------------------------------------------
extern "C" void kernel_launch(void* const* d_in, const int* in_sizes, int n_in,
                              void* d_out, int out_size) {
    const float* h   = (const float*)d_in[0];
    const int*   adj = (const int*)d_in[1];
    const float* W   = (const float*)d_in[2];
    const float* a   = (const float*)d_in[3];
    float* out = (float*)d_out;

    wh_gemm_kernel<<<(BB * NN) / 64, 256>>>(h, W);
    proj_kernel<<<(BB * NN) / 8, 256>>>(a);
    transpose_split_kernel<<<dim3(NN / 32, FOUT / 32, BB), dim3(32, 8)>>>();

    cudaFuncSetAttribute(gat_attn_ws, cudaFuncAttributeMaxDynamicSharedMemorySize, SMEM_TOTAL);
    gat_attn_ws<<<dim3(NN / 128, BB), 384, SMEM_TOTAL>>>(adj, out);
}